// round 6
// baseline (speedup 1.0000x reference)
#include <cuda_runtime.h>
#include <cstdint>

#define BN 8
#define CN 16
#define HN 96
#define WN 96
#define HW (HN*WN)
#define CHW (CN*HW)
#define NPIX (BN*HW)          // 73728
#define HID 128
#define YDIM 48

// scratch (allocation-free rule: device globals)
__device__ __align__(16) float g_tmp[BN*CHW];
__device__ __align__(16) float g_pre[NPIX];     // alive_pre flag (1.0/0.0)

typedef unsigned long long u64;

// ---------------- f32x2 helpers ----------------
__device__ __forceinline__ u64 ffma2(u64 a, u64 b, u64 c) {
    u64 d;
    asm("fma.rn.f32x2 %0, %1, %2, %3;" : "=l"(d) : "l"(a), "l"(b), "l"(c));
    return d;
}
__device__ __forceinline__ u64 add2(u64 a, u64 b) {
    u64 d;
    asm("add.rn.f32x2 %0, %1, %2;" : "=l"(d) : "l"(a), "l"(b));
    return d;
}
__device__ __forceinline__ u64 pack2(float lo, float hi) {
    u64 d;
    asm("mov.b64 %0, {%1, %2};" : "=l"(d) : "f"(lo), "f"(hi));
    return d;
}
__device__ __forceinline__ void unpack2(u64 v, float& lo, float& hi) {
    asm("mov.b64 {%0, %1}, %2;" : "=f"(lo), "=f"(hi) : "l"(v));
}
__device__ __forceinline__ u64 relu2(u64 v) {
    float lo, hi; unpack2(v, lo, hi);
    return pack2(fmaxf(lo, 0.0f), fmaxf(hi, 0.0f));
}

// ---------------- threefry2x32 (JAX-compatible, partitionable) ----------------
__host__ __device__ __forceinline__ uint32_t rotl32(uint32_t x, int r) {
#ifdef __CUDA_ARCH__
    return __funnelshift_l(x, x, r);
#else
    return (x << r) | (x >> (32 - r));
#endif
}
__host__ __device__ __forceinline__ void tf_round(uint32_t& x0, uint32_t& x1, int r) {
    x0 += x1; x1 = rotl32(x1, r); x1 ^= x0;
}
struct U2 { uint32_t x, y; };
__host__ __device__ __forceinline__ U2 threefry2x32(uint32_t k0, uint32_t k1,
                                                    uint32_t x0, uint32_t x1) {
    uint32_t k2 = k0 ^ k1 ^ 0x1BD11BDAu;
    x0 += k0; x1 += k1;
    tf_round(x0,x1,13); tf_round(x0,x1,15); tf_round(x0,x1,26); tf_round(x0,x1, 6);
    x0 += k1; x1 += k2 + 1u;
    tf_round(x0,x1,17); tf_round(x0,x1,29); tf_round(x0,x1,16); tf_round(x0,x1,24);
    x0 += k2; x1 += k0 + 2u;
    tf_round(x0,x1,13); tf_round(x0,x1,15); tf_round(x0,x1,26); tf_round(x0,x1, 6);
    x0 += k0; x1 += k1 + 3u;
    tf_round(x0,x1,17); tf_round(x0,x1,29); tf_round(x0,x1,16); tf_round(x0,x1,24);
    x0 += k1; x1 += k2 + 4u;
    tf_round(x0,x1,13); tf_round(x0,x1,15); tf_round(x0,x1,26); tf_round(x0,x1, 6);
    x0 += k2; x1 += k0 + 5u;
    U2 r; r.x = x0; r.y = x1; return r;
}
__device__ __forceinline__ float upd_mask_val(uint32_t k0, uint32_t k1, uint32_t idx) {
    U2 r = threefry2x32(k0, k1, 0u, idx);
    uint32_t bits = r.x ^ r.y;
    return ((bits >> 9) > 0x400000u) ? 1.0f : 0.0f;
}

// ---------------- K1: perception + 2 GEMMs (f32x2, 2 px/thread) + update ----------------
__global__ __launch_bounds__(128)
void k_update(const float* __restrict__ xin,
              const float* __restrict__ w2,
              const float* __restrict__ w3,
              uint32_t key0, uint32_t key1) {
    // dynamic smem: duplicated weight pairs
    extern __shared__ __align__(16) float2 smem[];
    float2* s_w2p = smem;                  // HID*YDIM float2 = 48 KB
    float2* s_w3p = smem + HID * YDIM;     // CN*HID  float2 = 16 KB

    int tid = threadIdx.x;
    for (int i = tid; i < HID * YDIM; i += 128) {
        float wv = w2[i]; s_w2p[i] = make_float2(wv, wv);
    }
    for (int i = tid; i < CN * HID; i += 128) {
        float wv = w3[i]; s_w3p[i] = make_float2(wv, wv);
    }
    __syncthreads();

    int pr = blockIdx.x * 128 + tid;       // pixel-pair id, 0..NPIX/2-1
    int b   = pr / (HW / 2);
    int rem = pr - b * (HW / 2);
    int h   = rem / (WN / 2);
    int w   = (rem - h * (WN / 2)) * 2;    // even column of the pair

    const float* xb = xin + (size_t)b * CHW;

    // perception: y2[3c]=center, y2[3c+1]=sobel-x, y2[3c+2]=sobel-y, packed (A=w, B=w+1)
    u64 y2[YDIM];
    float moA = 0.0f, moB = 0.0f;          // alive_pre pools (zero-pad OK vs 0.1 thresh)
    bool r0ok = (h > 0), r2ok = (h < HN - 1);
    bool lOK = (w > 0), rOK = (w < WN - 2);
    #pragma unroll
    for (int c = 0; c < CN; c++) {
        const float* xp = xb + c * HW + h * WN + w;
        float n0[4], n1[4], n2[4];
        {
            const float* q = xp - WN;
            n0[0] = (r0ok && lOK) ? __ldg(q - 1) : 0.0f;
            n0[1] = r0ok ? __ldg(q)     : 0.0f;
            n0[2] = r0ok ? __ldg(q + 1) : 0.0f;
            n0[3] = (r0ok && rOK) ? __ldg(q + 2) : 0.0f;
        }
        {
            const float* q = xp;
            n1[0] = lOK ? __ldg(q - 1) : 0.0f;
            n1[1] = __ldg(q);
            n1[2] = __ldg(q + 1);
            n1[3] = rOK ? __ldg(q + 2) : 0.0f;
        }
        {
            const float* q = xp + WN;
            n2[0] = (r2ok && lOK) ? __ldg(q - 1) : 0.0f;
            n2[1] = r2ok ? __ldg(q)     : 0.0f;
            n2[2] = r2ok ? __ldg(q + 1) : 0.0f;
            n2[3] = (r2ok && rOK) ? __ldg(q + 2) : 0.0f;
        }
        float cs0 = n0[0] + 2.0f*n1[0] + n2[0];
        float cs1 = n0[1] + 2.0f*n1[1] + n2[1];
        float cs2 = n0[2] + 2.0f*n1[2] + n2[2];
        float cs3 = n0[3] + 2.0f*n1[3] + n2[3];
        float rA0 = n0[0] + 2.0f*n0[1] + n0[2], rB0 = n0[1] + 2.0f*n0[2] + n0[3];
        float rA2 = n2[0] + 2.0f*n2[1] + n2[2], rB2 = n2[1] + 2.0f*n2[2] + n2[3];
        y2[3*c+0] = pack2(n1[1], n1[2]);
        y2[3*c+1] = pack2((cs2 - cs0) * 0.125f, (cs3 - cs1) * 0.125f);
        y2[3*c+2] = pack2((rA2 - rA0) * 0.125f, (rB2 - rB0) * 0.125f);
        if (c == 3) {
            float a = fmaxf(fmaxf(fmaxf(n0[0],n0[1]),fmaxf(n0[2],n1[0])),
                            fmaxf(fmaxf(n1[1],n1[2]),fmaxf(fmaxf(n2[0],n2[1]),n2[2])));
            float bmax = fmaxf(fmaxf(fmaxf(n0[1],n0[2]),fmaxf(n0[3],n1[1])),
                               fmaxf(fmaxf(n1[2],n1[3]),fmaxf(fmaxf(n2[1],n2[2]),n2[3])));
            moA = a; moB = bmax;
        }
    }

    u64 d2[CN];
    #pragma unroll
    for (int c = 0; c < CN; c++) d2[c] = 0ull;

    // hv = relu(W2 @ y); d = W3 @ hv — f32x2 over the pixel pair
    #pragma unroll 1
    for (int o = 0; o < HID; o += 4) {
        u64 hv[4];
        #pragma unroll
        for (int u = 0; u < 4; u++) {
            const ulonglong2* wr = (const ulonglong2*)(s_w2p + (o + u) * YDIM);
            u64 a0 = 0ull, a1 = 0ull, a2 = 0ull, a3 = 0ull;
            #pragma unroll
            for (int k = 0; k < 12; k++) {
                ulonglong2 wva = wr[2*k];
                ulonglong2 wvb = wr[2*k+1];
                a0 = ffma2(wva.x, y2[4*k+0], a0);
                a1 = ffma2(wva.y, y2[4*k+1], a1);
                a2 = ffma2(wvb.x, y2[4*k+2], a2);
                a3 = ffma2(wvb.y, y2[4*k+3], a3);
            }
            hv[u] = relu2(add2(add2(a0, a1), add2(a2, a3)));
        }
        #pragma unroll
        for (int c = 0; c < CN; c++) {
            const ulonglong2* w3r = (const ulonglong2*)(s_w3p + c * HID + o);
            ulonglong2 wva = w3r[0];
            ulonglong2 wvb = w3r[1];
            d2[c] = ffma2(wva.x, hv[0], ffma2(wva.y, hv[1],
                    ffma2(wvb.x, hv[2], ffma2(wvb.y, hv[3], d2[c]))));
        }
    }

    // alive_pre flags
    int p0 = b * HW + h * WN + w;
    *(float2*)(g_pre + p0) = make_float2(moA > 0.1f ? 1.0f : 0.0f,
                                         moB > 0.1f ? 1.0f : 0.0f);

    // stochastic update: g_tmp = x + mask * d
    uint32_t base = (uint32_t)(b * CHW + h * WN + w);
    #pragma unroll
    for (int c = 0; c < CN; c++) {
        float mA = upd_mask_val(key0, key1, base + (uint32_t)(c * HW));
        float mB = upd_mask_val(key0, key1, base + (uint32_t)(c * HW) + 1u);
        float xA, xB, dA, dB;
        unpack2(y2[3*c], xA, xB);
        unpack2(d2[c],   dA, dB);
        *(float2*)(g_tmp + b * CHW + c * HW + h * WN + w)
            = make_float2(fmaf(mA, dA, xA), fmaf(mB, dB, xB));
    }
}

// ---------------- K2: alive gating + write frame (4 px/thread, float4) ----------------
__global__ __launch_bounds__(128)
void k_mask(float* __restrict__ xout) {
    int q = blockIdx.x * 128 + threadIdx.x;   // 0..NPIX/4-1
    int b   = q / (HW / 4);
    int rem = q - b * (HW / 4);
    int h   = rem / (WN / 4);
    int w   = (rem - h * (WN / 4)) * 4;

    const float* an = g_tmp + (size_t)b * CHW + 3 * HW;

    float cm0 = -1e30f, cm1 = -1e30f, cm2 = -1e30f,
          cm3 = -1e30f, cm4 = -1e30f, cm5 = -1e30f;
    #pragma unroll
    for (int dr = -1; dr <= 1; dr++) {
        int r = h + dr;
        if (r >= 0 && r < HN) {
            const float* row = an + r * WN + w;
            float4 v = *(const float4*)row;
            cm1 = fmaxf(cm1, v.x); cm2 = fmaxf(cm2, v.y);
            cm3 = fmaxf(cm3, v.z); cm4 = fmaxf(cm4, v.w);
            if (w > 0)       cm0 = fmaxf(cm0, __ldg(row - 1));
            if (w < WN - 4)  cm5 = fmaxf(cm5, __ldg(row + 4));
        }
    }
    float mn0 = fmaxf(fmaxf(cm0, cm1), cm2);
    float mn1 = fmaxf(fmaxf(cm1, cm2), cm3);
    float mn2 = fmaxf(fmaxf(cm2, cm3), cm4);
    float mn3 = fmaxf(fmaxf(cm3, cm4), cm5);

    float4 pre = *(const float4*)(g_pre + b * HW + h * WN + w);
    float m0 = (pre.x != 0.0f && mn0 > 0.1f) ? 1.0f : 0.0f;
    float m1 = (pre.y != 0.0f && mn1 > 0.1f) ? 1.0f : 0.0f;
    float m2 = (pre.z != 0.0f && mn2 > 0.1f) ? 1.0f : 0.0f;
    float m3 = (pre.w != 0.0f && mn3 > 0.1f) ? 1.0f : 0.0f;

    #pragma unroll
    for (int c = 0; c < CN; c++) {
        int idx = b * CHW + c * HW + h * WN + w;
        float4 v = *(const float4*)(g_tmp + idx);
        v.x *= m0; v.y *= m1; v.z *= m2; v.w *= m3;
        *(float4*)(xout + idx) = v;
    }
}

// ---------------- launch ----------------
extern "C" void kernel_launch(void* const* d_in, const int* in_sizes, int n_in,
                              void* d_out, int out_size) {
    const float* x  = nullptr;
    const float* w2 = nullptr;
    const float* w3 = nullptr;
    for (int i = 0; i < n_in; i++) {
        if      (in_sizes[i] == BN*CHW)   x  = (const float*)d_in[i];
        else if (in_sizes[i] == HID*YDIM) w2 = (const float*)d_in[i];
        else if (in_sizes[i] == CN*HID)   w3 = (const float*)d_in[i];
    }
    float* out = (float*)d_out;
    int T = out_size / (BN * CHW);   // 24

    const int SMEM = (HID*YDIM + CN*HID) * (int)sizeof(float2);  // 64 KB
    cudaFuncSetAttribute(k_update, cudaFuncAttributeMaxDynamicSharedMemorySize, SMEM);

    const int gridU = (NPIX / 2) / 128;   // 288
    const int gridM = (NPIX / 4) / 128;   // 144
    const float* prev = x;
    for (int t = 0; t < T; t++) {
        U2 key = threefry2x32(0u, 42u, 0u, (uint32_t)t);
        k_update<<<gridU, 128, SMEM>>>(prev, w2, w3, key.x, key.y);
        float* dst = out + (size_t)t * BN * CHW;
        k_mask<<<gridM, 128>>>(dst);
        prev = dst;
    }
}

// round 10
// speedup vs baseline: 1.4333x; 1.4333x over previous
#include <cuda_runtime.h>
#include <cstdint>

#define BN 8
#define CN 16
#define HN 96
#define WN 96
#define HW (HN*WN)
#define CHW (CN*HW)
#define NPIX (BN*HW)          // 73728
#define HID 128
#define YDIM 48

// scratch (allocation-free rule: device globals)
__device__ __align__(16) float g_tmp[BN*CHW];
__device__ __align__(16) float g_pre[NPIX];     // alive_pre flag (1.0/0.0)

typedef unsigned long long u64;

// ---------------- f32x2 helpers ----------------
__device__ __forceinline__ u64 ffma2(u64 a, u64 b, u64 c) {
    u64 d;
    asm("fma.rn.f32x2 %0, %1, %2, %3;" : "=l"(d) : "l"(a), "l"(b), "l"(c));
    return d;
}
__device__ __forceinline__ u64 add2(u64 a, u64 b) {
    u64 d;
    asm("add.rn.f32x2 %0, %1, %2;" : "=l"(d) : "l"(a), "l"(b));
    return d;
}
__device__ __forceinline__ u64 pack2(float lo, float hi) {
    u64 d;
    asm("mov.b64 %0, {%1, %2};" : "=l"(d) : "f"(lo), "f"(hi));
    return d;
}
__device__ __forceinline__ void unpack2(u64 v, float& lo, float& hi) {
    asm("mov.b64 {%0, %1}, %2;" : "=f"(lo), "=f"(hi) : "l"(v));
}

// ---------------- threefry2x32 (JAX-compatible, partitionable) ----------------
__host__ __device__ __forceinline__ uint32_t rotl32(uint32_t x, int r) {
#ifdef __CUDA_ARCH__
    return __funnelshift_l(x, x, r);
#else
    return (x << r) | (x >> (32 - r));
#endif
}
__host__ __device__ __forceinline__ void tf_round(uint32_t& x0, uint32_t& x1, int r) {
    x0 += x1; x1 = rotl32(x1, r); x1 ^= x0;
}
struct U2 { uint32_t x, y; };
__host__ __device__ __forceinline__ U2 threefry2x32(uint32_t k0, uint32_t k1,
                                                    uint32_t x0, uint32_t x1) {
    uint32_t k2 = k0 ^ k1 ^ 0x1BD11BDAu;
    x0 += k0; x1 += k1;
    tf_round(x0,x1,13); tf_round(x0,x1,15); tf_round(x0,x1,26); tf_round(x0,x1, 6);
    x0 += k1; x1 += k2 + 1u;
    tf_round(x0,x1,17); tf_round(x0,x1,29); tf_round(x0,x1,16); tf_round(x0,x1,24);
    x0 += k2; x1 += k0 + 2u;
    tf_round(x0,x1,13); tf_round(x0,x1,15); tf_round(x0,x1,26); tf_round(x0,x1, 6);
    x0 += k0; x1 += k1 + 3u;
    tf_round(x0,x1,17); tf_round(x0,x1,29); tf_round(x0,x1,16); tf_round(x0,x1,24);
    x0 += k1; x1 += k2 + 4u;
    tf_round(x0,x1,13); tf_round(x0,x1,15); tf_round(x0,x1,26); tf_round(x0,x1, 6);
    x0 += k2; x1 += k0 + 5u;
    U2 r; r.x = x0; r.y = x1; return r;
}
__device__ __forceinline__ float upd_mask_val(uint32_t k0, uint32_t k1, uint32_t idx) {
    U2 r = threefry2x32(k0, k1, 0u, idx);
    uint32_t bits = r.x ^ r.y;
    return ((bits >> 9) > 0x400000u) ? 1.0f : 0.0f;
}

// ---------------- K1: perception + 2 GEMMs (f32x2 packed along K) + update ----------------
__global__ __launch_bounds__(256)
void k_update(const float* __restrict__ xin,
              const float* __restrict__ w2,
              const float* __restrict__ w3,
              uint32_t key0, uint32_t key1) {
    __shared__ __align__(16) float s_w2[HID*YDIM];   // 24 KB, row o: 48 floats (16B-aligned rows)
    __shared__ __align__(16) float s_w3[CN*HID];     // 8 KB,  row c: 128 floats

    int tid = threadIdx.x;
    for (int i = tid; i < HID*YDIM; i += 256) s_w2[i] = w2[i];
    for (int i = tid; i < CN*HID;  i += 256) s_w3[i] = w3[i];
    __syncthreads();

    int p = blockIdx.x * 256 + tid;      // pixel id
    int b  = p / HW;
    int hw = p - b * HW;
    int h  = hw / WN, w = hw - h * WN;

    const float* xb = xin + (size_t)b * CHW;

    // perception: y[3c]=center, y[3c+1]=sobel-x, y[3c+2]=sobel-y; packed as
    // y2[j] = (y[2j], y[2j+1]) for the K-dimension f32x2 dot products.
    float y[YDIM];
    float mo = 0.0f;                     // alive_pre pool (zero-pad OK vs 0.1 thresh)
    #pragma unroll
    for (int c = 0; c < CN; c++) {
        const float* xp = xb + c * HW;
        float n[3][3];
        #pragma unroll
        for (int di = 0; di < 3; di++) {
            #pragma unroll
            for (int dj = 0; dj < 3; dj++) {
                int hh = h + di - 1, ww = w + dj - 1;
                n[di][dj] = (hh >= 0 && hh < HN && ww >= 0 && ww < WN)
                            ? __ldg(xp + hh * WN + ww) : 0.0f;
            }
        }
        y[3*c+0] = n[1][1];
        float cs0 = n[0][0] + 2.0f*n[1][0] + n[2][0];
        float cs2 = n[0][2] + 2.0f*n[1][2] + n[2][2];
        y[3*c+1] = (cs2 - cs0) * 0.125f;
        float rs0 = n[0][0] + 2.0f*n[0][1] + n[0][2];
        float rs2 = n[2][0] + 2.0f*n[2][1] + n[2][2];
        y[3*c+2] = (rs2 - rs0) * 0.125f;
        if (c == 3) {
            mo = fmaxf(fmaxf(fmaxf(n[0][0],n[0][1]),fmaxf(n[0][2],n[1][0])),
                 fmaxf(fmaxf(n[1][1],n[1][2]),fmaxf(fmaxf(n[2][0],n[2][1]),n[2][2])));
        }
    }

    // pack y into 24 u64 pairs (register-pair aliasing; near-free)
    u64 y2[YDIM/2];
    #pragma unroll
    for (int j = 0; j < YDIM/2; j++) y2[j] = pack2(y[2*j], y[2*j+1]);

    u64 d2[CN];
    #pragma unroll
    for (int c = 0; c < CN; c++) d2[c] = 0ull;

    // hv = relu(W2 @ y); d = W3 @ hv — f32x2 along the K dimension
    #pragma unroll 1
    for (int o = 0; o < HID; o += 4) {
        float hv[4];
        #pragma unroll
        for (int u = 0; u < 4; u++) {
            const ulonglong2* wr = (const ulonglong2*)(s_w2 + (o + u) * YDIM);
            u64 a0 = 0ull, a1 = 0ull;
            #pragma unroll
            for (int k = 0; k < 12; k++) {
                ulonglong2 wv = wr[k];             // (w[4k],w[4k+1]) , (w[4k+2],w[4k+3])
                a0 = ffma2(wv.x, y2[2*k+0], a0);
                a1 = ffma2(wv.y, y2[2*k+1], a1);
            }
            u64 s = add2(a0, a1);
            float lo, hi; unpack2(s, lo, hi);
            hv[u] = fmaxf(lo + hi, 0.0f);
        }
        u64 h01 = pack2(hv[0], hv[1]);
        u64 h23 = pack2(hv[2], hv[3]);
        #pragma unroll
        for (int c = 0; c < CN; c++) {
            const ulonglong2* w3r = (const ulonglong2*)(s_w3 + c * HID + o);
            ulonglong2 wv = *w3r;                  // (w[o],w[o+1]) , (w[o+2],w[o+3])
            d2[c] = ffma2(wv.x, h01, ffma2(wv.y, h23, d2[c]));
        }
    }

    // alive_pre flag
    g_pre[p] = (mo > 0.1f) ? 1.0f : 0.0f;

    // stochastic update: g_tmp = x + mask * d
    uint32_t base = (uint32_t)(b * CHW + hw);
    #pragma unroll
    for (int c = 0; c < CN; c++) {
        float m = upd_mask_val(key0, key1, base + (uint32_t)(c * HW));
        float dlo, dhi; unpack2(d2[c], dlo, dhi);
        float d = dlo + dhi;
        g_tmp[b * CHW + c * HW + hw] = fmaf(m, d, y[3*c]);
    }
}

// ---------------- K2: alive gating (post pool only; pre from g_pre) ----------------
__global__ __launch_bounds__(256)
void k_mask(float* __restrict__ xout) {
    int p = blockIdx.x * 256 + threadIdx.x;
    int b  = p / HW;
    int hw = p - b * HW;
    int h  = hw / WN, w = hw - h * WN;

    const float* a_new = g_tmp + (size_t)b * CHW + 3 * HW;

    float mn = -1e30f;
    #pragma unroll
    for (int di = -1; di <= 1; di++) {
        #pragma unroll
        for (int dj = -1; dj <= 1; dj++) {
            int hh = h + di, ww = w + dj;
            if (hh >= 0 && hh < HN && ww >= 0 && ww < WN)
                mn = fmaxf(mn, __ldg(a_new + hh * WN + ww));
        }
    }
    float m = (g_pre[p] != 0.0f && mn > 0.1f) ? 1.0f : 0.0f;

    #pragma unroll
    for (int c = 0; c < CN; c++) {
        int idx = b * CHW + c * HW + hw;
        xout[idx] = g_tmp[idx] * m;
    }
}

// ---------------- launch ----------------
extern "C" void kernel_launch(void* const* d_in, const int* in_sizes, int n_in,
                              void* d_out, int out_size) {
    const float* x  = nullptr;
    const float* w2 = nullptr;
    const float* w3 = nullptr;
    for (int i = 0; i < n_in; i++) {
        if      (in_sizes[i] == BN*CHW)   x  = (const float*)d_in[i];
        else if (in_sizes[i] == HID*YDIM) w2 = (const float*)d_in[i];
        else if (in_sizes[i] == CN*HID)   w3 = (const float*)d_in[i];
    }
    float* out = (float*)d_out;
    int T = out_size / (BN * CHW);   // 24

    const int grid = NPIX / 256;     // 288
    const float* prev = x;
    for (int t = 0; t < T; t++) {
        U2 key = threefry2x32(0u, 42u, 0u, (uint32_t)t);
        k_update<<<grid, 256>>>(prev, w2, w3, key.x, key.y);
        float* dst = out + (size_t)t * BN * CHW;
        k_mask<<<grid, 256>>>(dst);
        prev = dst;
    }
}

// round 11
// speedup vs baseline: 1.4342x; 1.0006x over previous
#include <cuda_runtime.h>
#include <cstdint>

#define BN 8
#define CN 16
#define HN 96
#define WN 96
#define HW (HN*WN)
#define CHW (CN*HW)
#define NPIX (BN*HW)          // 73728
#define HID 128
#define YDIM 48

// scratch (allocation-free rule: device globals)
__device__ __align__(16) float g_tmp[BN*CHW];
__device__ __align__(16) float g_pre[NPIX];     // alive_pre flag (1.0/0.0)

typedef unsigned long long u64;

// ---------------- f32x2 helpers ----------------
__device__ __forceinline__ u64 ffma2(u64 a, u64 b, u64 c) {
    u64 d;
    asm("fma.rn.f32x2 %0, %1, %2, %3;" : "=l"(d) : "l"(a), "l"(b), "l"(c));
    return d;
}
__device__ __forceinline__ u64 add2(u64 a, u64 b) {
    u64 d;
    asm("add.rn.f32x2 %0, %1, %2;" : "=l"(d) : "l"(a), "l"(b));
    return d;
}
__device__ __forceinline__ u64 pack2(float lo, float hi) {
    u64 d;
    asm("mov.b64 %0, {%1, %2};" : "=l"(d) : "f"(lo), "f"(hi));
    return d;
}
__device__ __forceinline__ void unpack2(u64 v, float& lo, float& hi) {
    asm("mov.b64 {%0, %1}, %2;" : "=f"(lo), "=f"(hi) : "l"(v));
}

// ---------------- threefry2x32 (JAX-compatible, partitionable) ----------------
__host__ __device__ __forceinline__ uint32_t rotl32(uint32_t x, int r) {
#ifdef __CUDA_ARCH__
    return __funnelshift_l(x, x, r);
#else
    return (x << r) | (x >> (32 - r));
#endif
}
__host__ __device__ __forceinline__ void tf_round(uint32_t& x0, uint32_t& x1, int r) {
    x0 += x1; x1 = rotl32(x1, r); x1 ^= x0;
}
struct U2 { uint32_t x, y; };
__host__ __device__ __forceinline__ U2 threefry2x32(uint32_t k0, uint32_t k1,
                                                    uint32_t x0, uint32_t x1) {
    uint32_t k2 = k0 ^ k1 ^ 0x1BD11BDAu;
    x0 += k0; x1 += k1;
    tf_round(x0,x1,13); tf_round(x0,x1,15); tf_round(x0,x1,26); tf_round(x0,x1, 6);
    x0 += k1; x1 += k2 + 1u;
    tf_round(x0,x1,17); tf_round(x0,x1,29); tf_round(x0,x1,16); tf_round(x0,x1,24);
    x0 += k2; x1 += k0 + 2u;
    tf_round(x0,x1,13); tf_round(x0,x1,15); tf_round(x0,x1,26); tf_round(x0,x1, 6);
    x0 += k0; x1 += k1 + 3u;
    tf_round(x0,x1,17); tf_round(x0,x1,29); tf_round(x0,x1,16); tf_round(x0,x1,24);
    x0 += k1; x1 += k2 + 4u;
    tf_round(x0,x1,13); tf_round(x0,x1,15); tf_round(x0,x1,26); tf_round(x0,x1, 6);
    x0 += k2; x1 += k0 + 5u;
    U2 r; r.x = x0; r.y = x1; return r;
}
__device__ __forceinline__ float upd_mask_val(uint32_t k0, uint32_t k1, uint32_t idx) {
    U2 r = threefry2x32(k0, k1, 0u, idx);
    uint32_t bits = r.x ^ r.y;
    return ((bits >> 9) > 0x400000u) ? 1.0f : 0.0f;
}

// ---------------- K1: perception + 2 GEMMs (f32x2 packed along K) + update ----------------
__global__ __launch_bounds__(256)
void k_update(const float* __restrict__ xin,
              const float* __restrict__ w2,
              const float* __restrict__ w3,
              uint32_t key0, uint32_t key1) {
    __shared__ __align__(16) float s_w2[HID*YDIM];   // 24 KB
    __shared__ __align__(16) float s_w3[CN*HID];     // 8 KB

    int tid = threadIdx.x;
    for (int i = tid; i < HID*YDIM; i += 256) s_w2[i] = w2[i];
    for (int i = tid; i < CN*HID;  i += 256) s_w3[i] = w3[i];
    __syncthreads();

    int p = blockIdx.x * 256 + tid;      // pixel id
    int b  = p / HW;
    int hw = p - b * HW;
    int h  = hw / WN, w = hw - h * WN;

    const float* xb = xin + (size_t)b * CHW;

    float y[YDIM];
    float mo = 0.0f;                     // alive_pre pool (zero-pad OK vs 0.1 thresh)
    #pragma unroll
    for (int c = 0; c < CN; c++) {
        const float* xp = xb + c * HW;
        float n[3][3];
        #pragma unroll
        for (int di = 0; di < 3; di++) {
            #pragma unroll
            for (int dj = 0; dj < 3; dj++) {
                int hh = h + di - 1, ww = w + dj - 1;
                n[di][dj] = (hh >= 0 && hh < HN && ww >= 0 && ww < WN)
                            ? __ldg(xp + hh * WN + ww) : 0.0f;
            }
        }
        y[3*c+0] = n[1][1];
        float cs0 = n[0][0] + 2.0f*n[1][0] + n[2][0];
        float cs2 = n[0][2] + 2.0f*n[1][2] + n[2][2];
        y[3*c+1] = (cs2 - cs0) * 0.125f;
        float rs0 = n[0][0] + 2.0f*n[0][1] + n[0][2];
        float rs2 = n[2][0] + 2.0f*n[2][1] + n[2][2];
        y[3*c+2] = (rs2 - rs0) * 0.125f;
        if (c == 3) {
            mo = fmaxf(fmaxf(fmaxf(n[0][0],n[0][1]),fmaxf(n[0][2],n[1][0])),
                 fmaxf(fmaxf(n[1][1],n[1][2]),fmaxf(fmaxf(n[2][0],n[2][1]),n[2][2])));
        }
    }

    u64 y2[YDIM/2];
    #pragma unroll
    for (int j = 0; j < YDIM/2; j++) y2[j] = pack2(y[2*j], y[2*j+1]);

    u64 d2[CN];
    #pragma unroll
    for (int c = 0; c < CN; c++) d2[c] = 0ull;

    #pragma unroll 1
    for (int o = 0; o < HID; o += 4) {
        float hv[4];
        #pragma unroll
        for (int u = 0; u < 4; u++) {
            const ulonglong2* wr = (const ulonglong2*)(s_w2 + (o + u) * YDIM);
            u64 a0 = 0ull, a1 = 0ull;
            #pragma unroll
            for (int k = 0; k < 12; k++) {
                ulonglong2 wv = wr[k];
                a0 = ffma2(wv.x, y2[2*k+0], a0);
                a1 = ffma2(wv.y, y2[2*k+1], a1);
            }
            u64 s = add2(a0, a1);
            float lo, hi; unpack2(s, lo, hi);
            hv[u] = fmaxf(lo + hi, 0.0f);
        }
        u64 h01 = pack2(hv[0], hv[1]);
        u64 h23 = pack2(hv[2], hv[3]);
        #pragma unroll
        for (int c = 0; c < CN; c++) {
            const ulonglong2* w3r = (const ulonglong2*)(s_w3 + c * HID + o);
            ulonglong2 wv = *w3r;
            d2[c] = ffma2(wv.x, h01, ffma2(wv.y, h23, d2[c]));
        }
    }

    g_pre[p] = (mo > 0.1f) ? 1.0f : 0.0f;

    uint32_t base = (uint32_t)(b * CHW + hw);
    #pragma unroll
    for (int c = 0; c < CN; c++) {
        float m = upd_mask_val(key0, key1, base + (uint32_t)(c * HW));
        float dlo, dhi; unpack2(d2[c], dlo, dhi);
        float d = dlo + dhi;
        g_tmp[b * CHW + c * HW + hw] = fmaf(m, d, y[3*c]);
    }
}

// ---------------- K2: alive gating, 4 pixels x 1 channel per thread ----------------
// 294912 threads (4x old count): latency-bound kernel wants occupancy. Pool reads
// are L2-hot (g_tmp just written). Redundant pool recompute per channel is free.
__global__ __launch_bounds__(256)
void k_mask(float* __restrict__ xout) {
    int q = blockIdx.x * 256 + threadIdx.x;       // 0 .. NPIX/4*16 - 1
    int idx4 = q & (NPIX/4 - 1);                  // pixel-quad id (NPIX/4 = 18432, pow2)
    int c    = q >> 14;                           // channel 0..15  (q / 16384)
    // NPIX/4 = 18432 is NOT a power of two (18432 = 2^11*9). Use div instead:
    c    = q / (NPIX/4);
    idx4 = q - c * (NPIX/4);

    int p0 = idx4 * 4;
    int b  = p0 / HW;
    int hw = p0 - b * HW;
    int h  = hw / WN, w = hw - h * WN;            // w in {0,4,...,92}

    const float* an = g_tmp + (size_t)b * CHW + 3 * HW;

    // column maxes over rows h-1..h+1 for columns w-1 .. w+4
    float cm0 = -1e30f, cm1 = -1e30f, cm2 = -1e30f,
          cm3 = -1e30f, cm4 = -1e30f, cm5 = -1e30f;
    #pragma unroll
    for (int dr = -1; dr <= 1; dr++) {
        int r = h + dr;
        if (r >= 0 && r < HN) {
            const float* row = an + r * WN + w;
            float4 v = *(const float4*)row;
            cm1 = fmaxf(cm1, v.x); cm2 = fmaxf(cm2, v.y);
            cm3 = fmaxf(cm3, v.z); cm4 = fmaxf(cm4, v.w);
            if (w > 0)       cm0 = fmaxf(cm0, __ldg(row - 1));
            if (w < WN - 4)  cm5 = fmaxf(cm5, __ldg(row + 4));
        }
    }
    float mn0 = fmaxf(fmaxf(cm0, cm1), cm2);
    float mn1 = fmaxf(fmaxf(cm1, cm2), cm3);
    float mn2 = fmaxf(fmaxf(cm2, cm3), cm4);
    float mn3 = fmaxf(fmaxf(cm3, cm4), cm5);

    float4 pre = *(const float4*)(g_pre + b * HW + hw);
    float m0 = (pre.x != 0.0f && mn0 > 0.1f) ? 1.0f : 0.0f;
    float m1 = (pre.y != 0.0f && mn1 > 0.1f) ? 1.0f : 0.0f;
    float m2 = (pre.z != 0.0f && mn2 > 0.1f) ? 1.0f : 0.0f;
    float m3 = (pre.w != 0.0f && mn3 > 0.1f) ? 1.0f : 0.0f;

    int idx = b * CHW + c * HW + hw;
    float4 v = *(const float4*)(g_tmp + idx);
    v.x *= m0; v.y *= m1; v.z *= m2; v.w *= m3;
    *(float4*)(xout + idx) = v;
}

// ---------------- launch ----------------
extern "C" void kernel_launch(void* const* d_in, const int* in_sizes, int n_in,
                              void* d_out, int out_size) {
    const float* x  = nullptr;
    const float* w2 = nullptr;
    const float* w3 = nullptr;
    for (int i = 0; i < n_in; i++) {
        if      (in_sizes[i] == BN*CHW)   x  = (const float*)d_in[i];
        else if (in_sizes[i] == HID*YDIM) w2 = (const float*)d_in[i];
        else if (in_sizes[i] == CN*HID)   w3 = (const float*)d_in[i];
    }
    float* out = (float*)d_out;
    int T = out_size / (BN * CHW);   // 24

    const int gridU = NPIX / 256;                 // 288
    const int gridM = (NPIX / 4) * CN / 256;      // 1152
    const float* prev = x;
    for (int t = 0; t < T; t++) {
        U2 key = threefry2x32(0u, 42u, 0u, (uint32_t)t);
        k_update<<<gridU, 256>>>(prev, w2, w3, key.x, key.y);
        float* dst = out + (size_t)t * BN * CHW;
        k_mask<<<gridM, 256>>>(dst);
        prev = dst;
    }
}

// round 14
// speedup vs baseline: 1.4472x; 1.0091x over previous
#include <cuda_runtime.h>
#include <cstdint>

#define BN 8
#define CN 16
#define HN 96
#define WN 96
#define HW (HN*WN)
#define CHW (CN*HW)
#define NPIX (BN*HW)          // 73728
#define HID 128
#define YDIM 48

// scratch (allocation-free rule: device globals)
__device__ __align__(16) float g_tmp[BN*CHW];
__device__ __align__(16) float g_pre[NPIX];     // alive_pre flag (1.0/0.0)

typedef unsigned long long u64;

// weights in constant memory: uniform-index access -> LDCU -> UR operands,
// so FFMA2 reads only 2 distinct even + 2 distinct odd GPRs (rt 2, not 3).
// layout: c_w2p[o*12 + k] = (w2[o][4k],w2[o][4k+1]) , (w2[o][4k+2],w2[o][4k+3])
//         c_w3p[c*32 + j] = (w3[c][4j],w3[c][4j+1]) , (w3[c][4j+2],w3[c][4j+3])
__constant__ __align__(16) ulonglong2 c_w2p[HID*YDIM/4];   // 24 KB
__constant__ __align__(16) ulonglong2 c_w3p[CN*HID/4];     // 8 KB

// ---------------- f32x2 helpers ----------------
__device__ __forceinline__ u64 ffma2(u64 a, u64 b, u64 c) {
    u64 d;
    asm("fma.rn.f32x2 %0, %1, %2, %3;" : "=l"(d) : "l"(a), "l"(b), "l"(c));
    return d;
}
__device__ __forceinline__ u64 add2(u64 a, u64 b) {
    u64 d;
    asm("add.rn.f32x2 %0, %1, %2;" : "=l"(d) : "l"(a), "l"(b));
    return d;
}
__device__ __forceinline__ u64 pack2(float lo, float hi) {
    u64 d;
    asm("mov.b64 %0, {%1, %2};" : "=l"(d) : "f"(lo), "f"(hi));
    return d;
}
__device__ __forceinline__ void unpack2(u64 v, float& lo, float& hi) {
    asm("mov.b64 {%0, %1}, %2;" : "=f"(lo), "=f"(hi) : "l"(v));
}

// ---------------- threefry2x32 (JAX-compatible, partitionable) ----------------
__host__ __device__ __forceinline__ uint32_t rotl32(uint32_t x, int r) {
#ifdef __CUDA_ARCH__
    return __funnelshift_l(x, x, r);
#else
    return (x << r) | (x >> (32 - r));
#endif
}
__host__ __device__ __forceinline__ void tf_round(uint32_t& x0, uint32_t& x1, int r) {
    x0 += x1; x1 = rotl32(x1, r); x1 ^= x0;
}
struct U2 { uint32_t x, y; };
__host__ __device__ __forceinline__ U2 threefry2x32(uint32_t k0, uint32_t k1,
                                                    uint32_t x0, uint32_t x1) {
    uint32_t k2 = k0 ^ k1 ^ 0x1BD11BDAu;
    x0 += k0; x1 += k1;
    tf_round(x0,x1,13); tf_round(x0,x1,15); tf_round(x0,x1,26); tf_round(x0,x1, 6);
    x0 += k1; x1 += k2 + 1u;
    tf_round(x0,x1,17); tf_round(x0,x1,29); tf_round(x0,x1,16); tf_round(x0,x1,24);
    x0 += k2; x1 += k0 + 2u;
    tf_round(x0,x1,13); tf_round(x0,x1,15); tf_round(x0,x1,26); tf_round(x0,x1, 6);
    x0 += k0; x1 += k1 + 3u;
    tf_round(x0,x1,17); tf_round(x0,x1,29); tf_round(x0,x1,16); tf_round(x0,x1,24);
    x0 += k1; x1 += k2 + 4u;
    tf_round(x0,x1,13); tf_round(x0,x1,15); tf_round(x0,x1,26); tf_round(x0,x1, 6);
    x0 += k2; x1 += k0 + 5u;
    U2 r; r.x = x0; r.y = x1; return r;
}
__device__ __forceinline__ float upd_mask_val(uint32_t k0, uint32_t k1, uint32_t idx) {
    U2 r = threefry2x32(k0, k1, 0u, idx);
    uint32_t bits = r.x ^ r.y;
    return ((bits >> 9) > 0x400000u) ? 1.0f : 0.0f;
}

// ---------------- K1: perception + 2 GEMMs (f32x2, weights in cbank/UR) + update ----------------
__global__ __launch_bounds__(256)
void k_update(const float* __restrict__ xin,
              uint32_t key0, uint32_t key1) {
    int tid = threadIdx.x;
    int p = blockIdx.x * 256 + tid;      // pixel id
    int b  = p / HW;
    int hw = p - b * HW;
    int h  = hw / WN, w = hw - h * WN;

    const float* xb = xin + (size_t)b * CHW;

    float y[YDIM];
    float mo = 0.0f;                     // alive_pre pool (zero-pad OK vs 0.1 thresh)
    #pragma unroll
    for (int c = 0; c < CN; c++) {
        const float* xp = xb + c * HW;
        float n[3][3];
        #pragma unroll
        for (int di = 0; di < 3; di++) {
            #pragma unroll
            for (int dj = 0; dj < 3; dj++) {
                int hh = h + di - 1, ww = w + dj - 1;
                n[di][dj] = (hh >= 0 && hh < HN && ww >= 0 && ww < WN)
                            ? __ldg(xp + hh * WN + ww) : 0.0f;
            }
        }
        y[3*c+0] = n[1][1];
        float cs0 = n[0][0] + 2.0f*n[1][0] + n[2][0];
        float cs2 = n[0][2] + 2.0f*n[1][2] + n[2][2];
        y[3*c+1] = (cs2 - cs0) * 0.125f;
        float rs0 = n[0][0] + 2.0f*n[0][1] + n[0][2];
        float rs2 = n[2][0] + 2.0f*n[2][1] + n[2][2];
        y[3*c+2] = (rs2 - rs0) * 0.125f;
        if (c == 3) {
            mo = fmaxf(fmaxf(fmaxf(n[0][0],n[0][1]),fmaxf(n[0][2],n[1][0])),
                 fmaxf(fmaxf(n[1][1],n[1][2]),fmaxf(fmaxf(n[2][0],n[2][1]),n[2][2])));
        }
    }

    // pack y into 24 u64 pairs (register-pair aliasing; near-free)
    u64 y2[YDIM/2];
    #pragma unroll
    for (int j = 0; j < YDIM/2; j++) y2[j] = pack2(y[2*j], y[2*j+1]);

    u64 d2[CN];
    #pragma unroll
    for (int c = 0; c < CN; c++) d2[c] = 0ull;

    // hv = relu(W2 @ y); d = W3 @ hv — f32x2 along K, weights via LDCU/UR
    #pragma unroll 1
    for (int o = 0; o < HID; o += 4) {
        float hv[4];
        #pragma unroll
        for (int u = 0; u < 4; u++) {
            u64 a0 = 0ull, a1 = 0ull;
            #pragma unroll
            for (int k = 0; k < 12; k++) {
                ulonglong2 wv = c_w2p[(o + u) * 12 + k];
                a0 = ffma2(wv.x, y2[2*k+0], a0);
                a1 = ffma2(wv.y, y2[2*k+1], a1);
            }
            u64 s = add2(a0, a1);
            float lo, hi; unpack2(s, lo, hi);
            hv[u] = fmaxf(lo + hi, 0.0f);
        }
        u64 h01 = pack2(hv[0], hv[1]);
        u64 h23 = pack2(hv[2], hv[3]);
        #pragma unroll
        for (int c = 0; c < CN; c++) {
            ulonglong2 wv = c_w3p[c * 32 + (o >> 2)];
            d2[c] = ffma2(wv.x, h01, ffma2(wv.y, h23, d2[c]));
        }
    }

    g_pre[p] = (mo > 0.1f) ? 1.0f : 0.0f;

    uint32_t base = (uint32_t)(b * CHW + hw);
    #pragma unroll
    for (int c = 0; c < CN; c++) {
        float m = upd_mask_val(key0, key1, base + (uint32_t)(c * HW));
        float dlo, dhi; unpack2(d2[c], dlo, dhi);
        float d = dlo + dhi;
        g_tmp[b * CHW + c * HW + hw] = fmaf(m, d, y[3*c]);
    }
}

// ---------------- K2: alive gating, 4 pixels x 1 channel per thread ----------------
__global__ __launch_bounds__(256)
void k_mask(float* __restrict__ xout) {
    int q = blockIdx.x * 256 + threadIdx.x;       // 0 .. NPIX/4*CN - 1
    int c    = q / (NPIX/4);
    int idx4 = q - c * (NPIX/4);

    int p0 = idx4 * 4;
    int b  = p0 / HW;
    int hw = p0 - b * HW;
    int h  = hw / WN, w = hw - h * WN;            // w in {0,4,...,92}

    const float* an = g_tmp + (size_t)b * CHW + 3 * HW;

    float cm0 = -1e30f, cm1 = -1e30f, cm2 = -1e30f,
          cm3 = -1e30f, cm4 = -1e30f, cm5 = -1e30f;
    #pragma unroll
    for (int dr = -1; dr <= 1; dr++) {
        int r = h + dr;
        if (r >= 0 && r < HN) {
            const float* row = an + r * WN + w;
            float4 v = *(const float4*)row;
            cm1 = fmaxf(cm1, v.x); cm2 = fmaxf(cm2, v.y);
            cm3 = fmaxf(cm3, v.z); cm4 = fmaxf(cm4, v.w);
            if (w > 0)       cm0 = fmaxf(cm0, __ldg(row - 1));
            if (w < WN - 4)  cm5 = fmaxf(cm5, __ldg(row + 4));
        }
    }
    float mn0 = fmaxf(fmaxf(cm0, cm1), cm2);
    float mn1 = fmaxf(fmaxf(cm1, cm2), cm3);
    float mn2 = fmaxf(fmaxf(cm2, cm3), cm4);
    float mn3 = fmaxf(fmaxf(cm3, cm4), cm5);

    float4 pre = *(const float4*)(g_pre + b * HW + hw);
    float m0 = (pre.x != 0.0f && mn0 > 0.1f) ? 1.0f : 0.0f;
    float m1 = (pre.y != 0.0f && mn1 > 0.1f) ? 1.0f : 0.0f;
    float m2 = (pre.z != 0.0f && mn2 > 0.1f) ? 1.0f : 0.0f;
    float m3 = (pre.w != 0.0f && mn3 > 0.1f) ? 1.0f : 0.0f;

    int idx = b * CHW + c * HW + hw;
    float4 v = *(const float4*)(g_tmp + idx);
    v.x *= m0; v.y *= m1; v.z *= m2; v.w *= m3;
    *(float4*)(xout + idx) = v;
}

// ---------------- launch ----------------
extern "C" void kernel_launch(void* const* d_in, const int* in_sizes, int n_in,
                              void* d_out, int out_size) {
    const float* x  = nullptr;
    const float* w2 = nullptr;
    const float* w3 = nullptr;
    for (int i = 0; i < n_in; i++) {
        if      (in_sizes[i] == BN*CHW)   x  = (const float*)d_in[i];
        else if (in_sizes[i] == HID*YDIM) w2 = (const float*)d_in[i];
        else if (in_sizes[i] == CN*HID)   w3 = (const float*)d_in[i];
    }
    float* out = (float*)d_out;
    int T = out_size / (BN * CHW);   // 24

    // stage weights into constant memory (D2D async memcpy: graph-capturable)
    cudaMemcpyToSymbolAsync(c_w2p, w2, HID*YDIM*sizeof(float), 0,
                            cudaMemcpyDeviceToDevice, 0);
    cudaMemcpyToSymbolAsync(c_w3p, w3, CN*HID*sizeof(float), 0,
                            cudaMemcpyDeviceToDevice, 0);

    const int gridU = NPIX / 256;                 // 288
    const int gridM = (NPIX / 4) * CN / 256;      // 1152
    const float* prev = x;
    for (int t = 0; t < T; t++) {
        U2 key = threefry2x32(0u, 42u, 0u, (uint32_t)t);
        k_update<<<gridU, 256>>>(prev, key.x, key.y);
        float* dst = out + (size_t)t * BN * CHW;
        k_mask<<<gridM, 256>>>(dst);
        prev = dst;
    }
}